// round 3
// baseline (speedup 1.0000x reference)
#include <cuda_runtime.h>
#include <math.h>

#define NN 50000
#define EE 800000
#define ALPHA_C 0.1f

// ---------------- scratch (device globals; no allocation allowed) ----------------
__device__ float g_t[NN * 128];    // GEMM output buffer (also N x 40 for conv3)
__device__ float g_h1[NN * 128];   // h1 (post relu)
__device__ float g_c[NN * 128];    // combined h
__device__ float g_d1[NN];         // dinv1 (unit weights)
__device__ float g_d2[NN];         // dinv2 (edge_weight), accumulates deg2 first
__device__ int   g_cnt[NN];        // in-degree counts
__device__ int   g_off[NN + 1];    // CSR offsets (by dst)
__device__ int   g_cur[NN];        // fill cursors
__device__ int2  g_pk1[EE];        // CSR slot: (src, bits(d1[src]))          conv1/conv3
__device__ int2  g_pk2[EE];        // CSR slot: (src, bits(d2[src]*ew))       conv2
__device__ int   g_is64;           // edge_index dtype flag

// ---------------- dtype helpers ----------------
__device__ __forceinline__ int load_src(const void* ei, int e) {
    return g_is64 ? (int)((const long long*)ei)[e] : ((const int*)ei)[e];
}
__device__ __forceinline__ int load_dst(const void* ei, int e) {
    return g_is64 ? (int)((const long long*)ei)[EE + e] : ((const int*)ei)[EE + e];
}

// int64 little-endian node ids < 2^31 => every odd int32 word is 0.
__global__ void detect_kernel(const int* ei32) {
    __shared__ int any;
    if (threadIdx.x == 0) any = 0;
    __syncthreads();
    int local = 0;
    for (int i = threadIdx.x; i < 4096; i += blockDim.x)
        if (ei32[2 * i + 1] != 0) local = 1;
    if (local) atomicOr(&any, 1);
    __syncthreads();
    if (threadIdx.x == 0) g_is64 = (any == 0) ? 1 : 0;
}

// ---------------- degree + CSR build ----------------
__global__ void zero_kernel() {
    int i = blockIdx.x * blockDim.x + threadIdx.x;
    if (i < NN) { g_cnt[i] = 0; g_d2[i] = 1.0f; }   // self-loop weight 1 for deg2
}

__global__ void count_kernel(const void* __restrict__ ei, const float* __restrict__ ew) {
    int e = blockIdx.x * blockDim.x + threadIdx.x;
    if (e >= EE) return;
    int d = load_dst(ei, e);
    atomicAdd(&g_cnt[d], 1);
    atomicAdd(&g_d2[d], ew[e]);
}

__global__ void dinv_kernel() {
    int i = blockIdx.x * blockDim.x + threadIdx.x;
    if (i < NN) {
        g_d1[i] = rsqrtf(1.0f + (float)g_cnt[i]);   // unit-weight degree incl. self-loop
        g_d2[i] = rsqrtf(g_d2[i]);
    }
}

// single-block scan over 50000 counts -> offsets + cursors
__global__ void scan_kernel() {
    __shared__ int tsum[1024];
    const int CH = (NN + 1023) / 1024;  // 49
    int t = threadIdx.x;
    int beg = t * CH, end = min(beg + CH, NN);
    int s = 0;
    for (int i = beg; i < end; i++) s += g_cnt[i];
    tsum[t] = s;
    __syncthreads();
    for (int off = 1; off < 1024; off <<= 1) {
        int v = (t >= off) ? tsum[t - off] : 0;
        __syncthreads();
        tsum[t] += v;
        __syncthreads();
    }
    int run = (t ? tsum[t - 1] : 0);
    for (int i = beg; i < end; i++) {
        int c = g_cnt[i];
        g_off[i] = run; g_cur[i] = run;
        run += c;
    }
    if (beg < NN && end == NN) g_off[NN] = run;
}

// fill CSR slots with pre-multiplied gather weights
__global__ void fill_kernel(const void* __restrict__ ei, const float* __restrict__ ew) {
    int e = blockIdx.x * blockDim.x + threadIdx.x;
    if (e >= EE) return;
    int s = load_src(ei, e);
    int d = load_dst(ei, e);
    int pos = atomicAdd(&g_cur[d], 1);
    float w1 = g_d1[s];
    float w2 = g_d2[s] * ew[e];
    g_pk1[pos] = make_int2(s, __float_as_int(w1));
    g_pk2[pos] = make_int2(s, __float_as_int(w2));
}

// ---------------- GEMM 128-col: T[NN,128] = X[NN,128] @ W[128,128] ----------------
// 64x128 tile, BK=32, 256 threads, 4x8 register tile per thread.
__global__ void gemm128_kernel(const float* __restrict__ X, const float* __restrict__ W,
                               float* __restrict__ T) {
    __shared__ float Xs[64][33];
    __shared__ float Ws[32][128];
    int tid  = threadIdx.x;
    int row0 = blockIdx.x * 64;
    int c0 = (tid & 15) * 8;
    int r0 = (tid >> 4) * 4;
    float acc[4][8] = {};

    for (int kk = 0; kk < 128; kk += 32) {
        #pragma unroll
        for (int f = tid; f < 512; f += 256) {
            int r = f >> 3, k4 = f & 7;
            int gr = row0 + r;
            float4 v = make_float4(0.f, 0.f, 0.f, 0.f);
            if (gr < NN) v = *(const float4*)(X + (size_t)gr * 128 + kk + k4 * 4);
            Xs[r][k4 * 4 + 0] = v.x; Xs[r][k4 * 4 + 1] = v.y;
            Xs[r][k4 * 4 + 2] = v.z; Xs[r][k4 * 4 + 3] = v.w;
        }
        #pragma unroll
        for (int f = tid; f < 1024; f += 256) {
            int k = f >> 5, c4 = f & 31;
            *(float4*)&Ws[k][c4 * 4] = *(const float4*)(W + (size_t)(kk + k) * 128 + c4 * 4);
        }
        __syncthreads();
        #pragma unroll
        for (int k = 0; k < 32; k++) {
            float4 w0 = *(const float4*)&Ws[k][c0];
            float4 w1 = *(const float4*)&Ws[k][c0 + 4];
            #pragma unroll
            for (int j = 0; j < 4; j++) {
                float xv = Xs[r0 + j][k];
                acc[j][0] += xv * w0.x; acc[j][1] += xv * w0.y;
                acc[j][2] += xv * w0.z; acc[j][3] += xv * w0.w;
                acc[j][4] += xv * w1.x; acc[j][5] += xv * w1.y;
                acc[j][6] += xv * w1.z; acc[j][7] += xv * w1.w;
            }
        }
        __syncthreads();
    }
    #pragma unroll
    for (int j = 0; j < 4; j++) {
        int gr = row0 + r0 + j;
        if (gr < NN) {
            *(float4*)(T + (size_t)gr * 128 + c0) =
                make_float4(acc[j][0], acc[j][1], acc[j][2], acc[j][3]);
            *(float4*)(T + (size_t)gr * 128 + c0 + 4) =
                make_float4(acc[j][4], acc[j][5], acc[j][6], acc[j][7]);
        }
    }
}

// ---------------- GEMM 40-col: T[NN,40] = X[NN,128] @ W[128,40] ----------------
// 64x64 tile (cols padded), 4x4 per thread
__global__ void gemm40_kernel(const float* __restrict__ X, const float* __restrict__ W,
                              float* __restrict__ T) {
    const int C = 40;
    __shared__ float Xs[64][33];
    __shared__ float Ws[32][64];
    int tid  = threadIdx.x;
    int row0 = blockIdx.x * 64;
    int c0 = (tid & 15) * 4;
    int r0 = (tid >> 4) * 4;
    float acc[4][4] = {};

    for (int kk = 0; kk < 128; kk += 32) {
        #pragma unroll
        for (int f = tid; f < 512; f += 256) {
            int r = f >> 3, k4 = f & 7;
            int gr = row0 + r;
            float4 v = make_float4(0.f, 0.f, 0.f, 0.f);
            if (gr < NN) v = *(const float4*)(X + (size_t)gr * 128 + kk + k4 * 4);
            Xs[r][k4 * 4 + 0] = v.x; Xs[r][k4 * 4 + 1] = v.y;
            Xs[r][k4 * 4 + 2] = v.z; Xs[r][k4 * 4 + 3] = v.w;
        }
        #pragma unroll
        for (int f = tid; f < 512; f += 256) {
            int k = f >> 4, c4 = f & 15;
            int gc = c4 * 4;
            float4 v = make_float4(0.f, 0.f, 0.f, 0.f);
            if (gc < C) v = *(const float4*)(W + (size_t)(kk + k) * C + gc);
            *(float4*)&Ws[k][c4 * 4] = v;
        }
        __syncthreads();
        #pragma unroll
        for (int k = 0; k < 32; k++) {
            float4 w = *(const float4*)&Ws[k][c0];
            #pragma unroll
            for (int j = 0; j < 4; j++) {
                float xv = Xs[r0 + j][k];
                acc[j][0] += xv * w.x; acc[j][1] += xv * w.y;
                acc[j][2] += xv * w.z; acc[j][3] += xv * w.w;
            }
        }
        __syncthreads();
    }
    #pragma unroll
    for (int j = 0; j < 4; j++) {
        int gr = row0 + r0 + j;
        if (gr < NN && c0 < C)
            *(float4*)(T + (size_t)gr * C + c0) =
                make_float4(acc[j][0], acc[j][1], acc[j][2], acc[j][3]);
    }
}

// ---------------- fused CSR aggregation, 128-wide (one warp per dst node) ----------------
// OUT[d] = epilogue( dinv[d] * ( dinv[d]*T[d] + sum_slots w*T[s] ) + b )
// mode 0: relu(.) -> h1      mode 1: 0.1*H1[d] + (.) -> combined h
__global__ void agg128_kernel(const float* __restrict__ T, float* __restrict__ OUT,
                              const int2* __restrict__ pk,
                              const float* __restrict__ dinv, const float* __restrict__ b,
                              const float* __restrict__ H1, int mode) {
    int gw = (blockIdx.x * blockDim.x + threadIdx.x) >> 5;
    if (gw >= NN) return;
    int lane = threadIdx.x & 31;
    const float4* T4 = (const float4*)T;

    float dd = dinv[gw];
    float4 acc = T4[(size_t)gw * 32 + lane];
    acc.x *= dd; acc.y *= dd; acc.z *= dd; acc.w *= dd;   // self-loop term (w=1)

    int i = g_off[gw], end = g_off[gw + 1];
    // unrolled by 4: independent loads raise MLP
    for (; i + 4 <= end; i += 4) {
        int2 p0 = pk[i], p1 = pk[i + 1], p2 = pk[i + 2], p3 = pk[i + 3];
        float4 v0 = T4[(size_t)p0.x * 32 + lane];
        float4 v1 = T4[(size_t)p1.x * 32 + lane];
        float4 v2 = T4[(size_t)p2.x * 32 + lane];
        float4 v3 = T4[(size_t)p3.x * 32 + lane];
        float w0 = __int_as_float(p0.y), w1 = __int_as_float(p1.y);
        float w2 = __int_as_float(p2.y), w3 = __int_as_float(p3.y);
        acc.x += v0.x * w0 + v1.x * w1 + v2.x * w2 + v3.x * w3;
        acc.y += v0.y * w0 + v1.y * w1 + v2.y * w2 + v3.y * w3;
        acc.z += v0.z * w0 + v1.z * w1 + v2.z * w2 + v3.z * w3;
        acc.w += v0.w * w0 + v1.w * w1 + v2.w * w2 + v3.w * w3;
    }
    for (; i < end; i++) {
        int2 p = pk[i];
        float w = __int_as_float(p.y);
        float4 v = T4[(size_t)p.x * 32 + lane];
        acc.x += v.x * w; acc.y += v.y * w; acc.z += v.z * w; acc.w += v.w * w;
    }

    float4 bb = ((const float4*)b)[lane];
    float4 r;
    r.x = acc.x * dd + bb.x; r.y = acc.y * dd + bb.y;
    r.z = acc.z * dd + bb.z; r.w = acc.w * dd + bb.w;
    if (mode == 0) {
        r.x = fmaxf(r.x, 0.f); r.y = fmaxf(r.y, 0.f);
        r.z = fmaxf(r.z, 0.f); r.w = fmaxf(r.w, 0.f);
    } else {
        float4 h = ((const float4*)H1)[(size_t)gw * 32 + lane];
        r.x += ALPHA_C * h.x; r.y += ALPHA_C * h.y;
        r.z += ALPHA_C * h.z; r.w += ALPHA_C * h.w;
    }
    ((float4*)OUT)[(size_t)gw * 32 + lane] = r;
}

// ---------------- fused CSR aggregation 40-wide + bias + log_softmax ----------------
// one warp per node; lanes 0..19 hold float2 each (40 floats total)
__global__ void agg40_lsm_kernel(const float* __restrict__ T, float* __restrict__ OUT,
                                 const int2* __restrict__ pk,
                                 const float* __restrict__ dinv, const float* __restrict__ b) {
    int gw = (blockIdx.x * blockDim.x + threadIdx.x) >> 5;
    if (gw >= NN) return;
    int lane = threadIdx.x & 31;
    const float2* T2 = (const float2*)T;
    bool act = (lane < 20);
    int li = act ? lane : 0;

    float dd = dinv[gw];
    float2 acc = make_float2(0.f, 0.f);
    {
        float2 v = T2[(size_t)gw * 20 + li];
        acc.x = v.x * dd; acc.y = v.y * dd;
    }
    int i = g_off[gw], end = g_off[gw + 1];
    for (; i + 4 <= end; i += 4) {
        int2 p0 = pk[i], p1 = pk[i + 1], p2 = pk[i + 2], p3 = pk[i + 3];
        float2 v0 = T2[(size_t)p0.x * 20 + li];
        float2 v1 = T2[(size_t)p1.x * 20 + li];
        float2 v2 = T2[(size_t)p2.x * 20 + li];
        float2 v3 = T2[(size_t)p3.x * 20 + li];
        float w0 = __int_as_float(p0.y), w1 = __int_as_float(p1.y);
        float w2 = __int_as_float(p2.y), w3 = __int_as_float(p3.y);
        acc.x += v0.x * w0 + v1.x * w1 + v2.x * w2 + v3.x * w3;
        acc.y += v0.y * w0 + v1.y * w1 + v2.y * w2 + v3.y * w3;
    }
    for (; i < end; i++) {
        int2 p = pk[i];
        float w = __int_as_float(p.y);
        float2 v = T2[(size_t)p.x * 20 + li];
        acc.x += v.x * w; acc.y += v.y * w;
    }
    float rx = -1e30f, ry = -1e30f;
    if (act) {
        float2 bb = ((const float2*)b)[lane];
        rx = acc.x * dd + bb.x;
        ry = acc.y * dd + bb.y;
    }
    float m = fmaxf(rx, ry);
    #pragma unroll
    for (int o = 16; o; o >>= 1) m = fmaxf(m, __shfl_xor_sync(0xffffffffu, m, o));
    float s_ = act ? (expf(rx - m) + expf(ry - m)) : 0.f;
    #pragma unroll
    for (int o = 16; o; o >>= 1) s_ += __shfl_xor_sync(0xffffffffu, s_, o);
    float l = m + logf(s_);
    if (act)
        ((float2*)OUT)[(size_t)gw * 20 + lane] = make_float2(rx - l, ry - l);
}

// ---------------- launch ----------------
extern "C" void kernel_launch(void* const* d_in, const int* in_sizes, int n_in,
                              void* d_out, int out_size) {
    const float* x  = (const float*)d_in[0];
    const void*  ei = d_in[1];
    const float* ew = (const float*)d_in[2];
    const float* W1 = (const float*)d_in[3];
    const float* b1 = (const float*)d_in[4];
    const float* W2 = (const float*)d_in[5];
    const float* b2 = (const float*)d_in[6];
    const float* W3 = (const float*)d_in[7];
    const float* b3 = (const float*)d_in[8];
    float* out = (float*)d_out;

    float *t, *h1, *c, *d1, *d2;
    int2 *pk1, *pk2;
    cudaGetSymbolAddress((void**)&t,   g_t);
    cudaGetSymbolAddress((void**)&h1,  g_h1);
    cudaGetSymbolAddress((void**)&c,   g_c);
    cudaGetSymbolAddress((void**)&d1,  g_d1);
    cudaGetSymbolAddress((void**)&d2,  g_d2);
    cudaGetSymbolAddress((void**)&pk1, g_pk1);
    cudaGetSymbolAddress((void**)&pk2, g_pk2);

    const int TB = 256;
    const int NB_N = (NN + TB - 1) / TB;
    const int NB_E = (EE + TB - 1) / TB;
    const int NB_W = (NN * 32 + TB - 1) / TB;   // one warp per node
    const int GB = (NN + 63) / 64;

    // graph prep (CSR by dst + both normalizations, pre-multiplied slot weights)
    detect_kernel<<<1, TB>>>((const int*)ei);
    zero_kernel<<<NB_N, TB>>>();
    count_kernel<<<NB_E, TB>>>(ei, ew);
    dinv_kernel<<<NB_N, TB>>>();
    scan_kernel<<<1, 1024>>>();
    fill_kernel<<<NB_E, TB>>>(ei, ew);

    // conv1: h1 = relu(agg_1(x@W1) + b1)
    gemm128_kernel<<<GB, TB>>>(x, W1, t);
    agg128_kernel<<<NB_W, TB>>>(t, h1, pk1, d1, b1, nullptr, 0);

    // conv2 (crf): c = 0.1*h1 + agg_w(h1@W2) + b2
    gemm128_kernel<<<GB, TB>>>(h1, W2, t);
    agg128_kernel<<<NB_W, TB>>>(t, c, pk2, d2, b2, h1, 1);

    // conv3: out = log_softmax(agg_1(c@W3) + b3)
    gemm40_kernel<<<GB, TB>>>(c, W3, t);
    agg40_lsm_kernel<<<NB_W, TB>>>(t, out, pk1, d1, b3);
}

// round 4
// speedup vs baseline: 1.1656x; 1.1656x over previous
#include <cuda_runtime.h>
#include <math.h>

#define NN 50000
#define EE 800000
#define ALPHA_C 0.1f

// ---------------- scratch (device globals; no allocation allowed) ----------------
__device__ float g_t[NN * 128];    // GEMM output buffer (also N x 40 for conv3)
__device__ float g_h1[NN * 128];   // h1 (post relu)
__device__ float g_c[NN * 128];    // combined h
__device__ float g_d1[NN];         // dinv1 (unit weights)
__device__ float g_d2[NN];         // dinv2 (edge_weight), accumulates deg2 first
__device__ int   g_cnt[NN];        // in-degree counts
__device__ int   g_off[NN + 1];    // CSR offsets (by dst)
__device__ int   g_cur[NN];        // fill cursors
__device__ int2  g_pk1[EE];        // CSR slot: (src, bits(d1[src]))      conv1/conv3
__device__ int2  g_pk2[EE];        // CSR slot: (src, bits(d2[src]*ew))   conv2
__device__ int   g_is64;           // edge_index dtype flag

// ---------------- dtype helpers ----------------
__device__ __forceinline__ int load_src(const void* ei, int e) {
    return g_is64 ? (int)((const long long*)ei)[e] : ((const int*)ei)[e];
}
__device__ __forceinline__ int load_dst(const void* ei, int e) {
    return g_is64 ? (int)((const long long*)ei)[EE + e] : ((const int*)ei)[EE + e];
}

// int64 little-endian node ids < 2^31 => every odd int32 word is 0.
__global__ void detect_kernel(const int* ei32) {
    __shared__ int any;
    if (threadIdx.x == 0) any = 0;
    __syncthreads();
    int local = 0;
    for (int i = threadIdx.x; i < 4096; i += blockDim.x)
        if (ei32[2 * i + 1] != 0) local = 1;
    if (local) atomicOr(&any, 1);
    __syncthreads();
    if (threadIdx.x == 0) g_is64 = (any == 0) ? 1 : 0;
}

// ---------------- degree + CSR build ----------------
__global__ void zero_kernel() {
    int i = blockIdx.x * blockDim.x + threadIdx.x;
    if (i < NN) { g_cnt[i] = 0; g_d2[i] = 1.0f; }   // self-loop weight 1 for deg2
}

__global__ void count_kernel(const void* __restrict__ ei, const float* __restrict__ ew) {
    int e = blockIdx.x * blockDim.x + threadIdx.x;
    if (e >= EE) return;
    int d = load_dst(ei, e);
    atomicAdd(&g_cnt[d], 1);
    atomicAdd(&g_d2[d], ew[e]);
}

__global__ void dinv_kernel() {
    int i = blockIdx.x * blockDim.x + threadIdx.x;
    if (i < NN) {
        g_d1[i] = rsqrtf(1.0f + (float)g_cnt[i]);   // unit-weight degree incl. self-loop
        g_d2[i] = rsqrtf(g_d2[i]);
    }
}

// single-block scan over 50000 counts -> offsets + cursors
__global__ void scan_kernel() {
    __shared__ int tsum[1024];
    const int CH = (NN + 1023) / 1024;  // 49
    int t = threadIdx.x;
    int beg = t * CH, end = min(beg + CH, NN);
    int s = 0;
    for (int i = beg; i < end; i++) s += g_cnt[i];
    tsum[t] = s;
    __syncthreads();
    for (int off = 1; off < 1024; off <<= 1) {
        int v = (t >= off) ? tsum[t - off] : 0;
        __syncthreads();
        tsum[t] += v;
        __syncthreads();
    }
    int run = (t ? tsum[t - 1] : 0);
    for (int i = beg; i < end; i++) {
        int c = g_cnt[i];
        g_off[i] = run; g_cur[i] = run;
        run += c;
    }
    if (beg < NN && end == NN) g_off[NN] = run;
}

// fill CSR slots with pre-multiplied gather weights
__global__ void fill_kernel(const void* __restrict__ ei, const float* __restrict__ ew) {
    int e = blockIdx.x * blockDim.x + threadIdx.x;
    if (e >= EE) return;
    int s = load_src(ei, e);
    int d = load_dst(ei, e);
    int pos = atomicAdd(&g_cur[d], 1);
    float w1 = g_d1[s];
    float w2 = g_d2[s] * ew[e];
    g_pk1[pos] = make_int2(s, __float_as_int(w1));
    g_pk2[pos] = make_int2(s, __float_as_int(w2));
}

// ---------------- GEMM: T[NN,C] = X[NN,128] @ W[128,C], C in {128,40} ----------------
// 64x64 tile, BK=32, 256 threads, 4x4 register tile. X tile stored k-major
// (transposed) so the inner loop is 2 conflict-free LDS.128 + 16 FFMA per k.
__global__ void gemm_kernel(const float* __restrict__ X, const float* __restrict__ W,
                            float* __restrict__ T, int C) {
    __shared__ float Xs[32][68];   // [k][row], stride 68 keeps 16B alignment for LDS.128
    __shared__ float Ws[32][64];   // [k][col]
    int tid  = threadIdx.x;
    int row0 = blockIdx.x * 64;
    int col0 = blockIdx.y * 64;
    int c0 = (tid & 15) * 4;
    int r0 = (tid >> 4) * 4;
    float acc[4][4] = {};

    for (int kk = 0; kk < 128; kk += 32) {
        // load X tile (64 rows x 32 k) transposed into Xs[k][row]
        #pragma unroll
        for (int f = tid; f < 512; f += 256) {
            int r = f >> 3, k4 = f & 7;
            int gr = row0 + r;
            float4 v = make_float4(0.f, 0.f, 0.f, 0.f);
            if (gr < NN) v = *(const float4*)(X + (size_t)gr * 128 + kk + k4 * 4);
            Xs[k4 * 4 + 0][r] = v.x;
            Xs[k4 * 4 + 1][r] = v.y;
            Xs[k4 * 4 + 2][r] = v.z;
            Xs[k4 * 4 + 3][r] = v.w;
        }
        // load W tile (32 k x 64 cols), zero-pad OOB cols
        #pragma unroll
        for (int f = tid; f < 512; f += 256) {
            int k = f >> 4, c4 = f & 15;
            int gc = col0 + c4 * 4;
            float4 v = make_float4(0.f, 0.f, 0.f, 0.f);
            if (gc < C) v = *(const float4*)(W + (size_t)(kk + k) * C + gc);
            *(float4*)&Ws[k][c4 * 4] = v;
        }
        __syncthreads();
        #pragma unroll
        for (int k = 0; k < 32; k++) {
            float4 xv = *(const float4*)&Xs[k][r0];   // 4 rows
            float4 w  = *(const float4*)&Ws[k][c0];   // 4 cols
            acc[0][0] += xv.x * w.x; acc[0][1] += xv.x * w.y;
            acc[0][2] += xv.x * w.z; acc[0][3] += xv.x * w.w;
            acc[1][0] += xv.y * w.x; acc[1][1] += xv.y * w.y;
            acc[1][2] += xv.y * w.z; acc[1][3] += xv.y * w.w;
            acc[2][0] += xv.z * w.x; acc[2][1] += xv.z * w.y;
            acc[2][2] += xv.z * w.z; acc[2][3] += xv.z * w.w;
            acc[3][0] += xv.w * w.x; acc[3][1] += xv.w * w.y;
            acc[3][2] += xv.w * w.z; acc[3][3] += xv.w * w.w;
        }
        __syncthreads();
    }
    #pragma unroll
    for (int j = 0; j < 4; j++) {
        int gr = row0 + r0 + j;
        int gc = col0 + c0;
        if (gr < NN && gc < C)
            *(float4*)(T + (size_t)gr * C + gc) =
                make_float4(acc[j][0], acc[j][1], acc[j][2], acc[j][3]);
    }
}

// ---------------- fused CSR aggregation, 128-wide (one warp per dst node) ----------------
// OUT[d] = epilogue( dinv[d] * ( dinv[d]*T[d] + sum_slots w*T[s] ) + b )
// mode 0: relu(.) -> h1      mode 1: 0.1*H1[d] + (.) -> combined h
__global__ void agg128_kernel(const float* __restrict__ T, float* __restrict__ OUT,
                              const int2* __restrict__ pk,
                              const float* __restrict__ dinv, const float* __restrict__ b,
                              const float* __restrict__ H1, int mode) {
    int gw = (blockIdx.x * blockDim.x + threadIdx.x) >> 5;
    if (gw >= NN) return;
    int lane = threadIdx.x & 31;
    const float4* T4 = (const float4*)T;

    float dd = dinv[gw];
    float4 acc = T4[(size_t)gw * 32 + lane];
    acc.x *= dd; acc.y *= dd; acc.z *= dd; acc.w *= dd;   // self-loop term (w=1)

    int beg = g_off[gw], end = g_off[gw + 1];
    for (int i = beg; i < end; i++) {
        int2 p = pk[i];
        float w = __int_as_float(p.y);
        float4 v = T4[(size_t)p.x * 32 + lane];
        acc.x += v.x * w; acc.y += v.y * w;
        acc.z += v.z * w; acc.w += v.w * w;
    }

    float4 bb = ((const float4*)b)[lane];
    float4 r;
    r.x = acc.x * dd + bb.x; r.y = acc.y * dd + bb.y;
    r.z = acc.z * dd + bb.z; r.w = acc.w * dd + bb.w;
    if (mode == 0) {
        r.x = fmaxf(r.x, 0.f); r.y = fmaxf(r.y, 0.f);
        r.z = fmaxf(r.z, 0.f); r.w = fmaxf(r.w, 0.f);
    } else {
        float4 h = ((const float4*)H1)[(size_t)gw * 32 + lane];
        r.x += ALPHA_C * h.x; r.y += ALPHA_C * h.y;
        r.z += ALPHA_C * h.z; r.w += ALPHA_C * h.w;
    }
    ((float4*)OUT)[(size_t)gw * 32 + lane] = r;
}

// ---------------- fused CSR aggregation 40-wide + bias + log_softmax ----------------
// one warp per node; lanes 0..19 hold float2 each (40 floats total)
__global__ void agg40_lsm_kernel(const float* __restrict__ T, float* __restrict__ OUT,
                                 const int2* __restrict__ pk,
                                 const float* __restrict__ dinv, const float* __restrict__ b) {
    int gw = (blockIdx.x * blockDim.x + threadIdx.x) >> 5;
    if (gw >= NN) return;
    int lane = threadIdx.x & 31;
    const float2* T2 = (const float2*)T;
    bool act = (lane < 20);
    int li = act ? lane : 0;

    float dd = dinv[gw];
    float2 acc;
    {
        float2 v = T2[(size_t)gw * 20 + li];
        acc.x = v.x * dd; acc.y = v.y * dd;
    }
    int beg = g_off[gw], end = g_off[gw + 1];
    for (int i = beg; i < end; i++) {
        int2 p = pk[i];
        float w = __int_as_float(p.y);
        float2 v = T2[(size_t)p.x * 20 + li];
        acc.x += v.x * w; acc.y += v.y * w;
    }
    float rx = -1e30f, ry = -1e30f;
    if (act) {
        float2 bb = ((const float2*)b)[lane];
        rx = acc.x * dd + bb.x;
        ry = acc.y * dd + bb.y;
    }
    float m = fmaxf(rx, ry);
    #pragma unroll
    for (int o = 16; o; o >>= 1) m = fmaxf(m, __shfl_xor_sync(0xffffffffu, m, o));
    float s_ = act ? (expf(rx - m) + expf(ry - m)) : 0.f;
    #pragma unroll
    for (int o = 16; o; o >>= 1) s_ += __shfl_xor_sync(0xffffffffu, s_, o);
    float l = m + logf(s_);
    if (act)
        ((float2*)OUT)[(size_t)gw * 20 + lane] = make_float2(rx - l, ry - l);
}

// ---------------- launch ----------------
extern "C" void kernel_launch(void* const* d_in, const int* in_sizes, int n_in,
                              void* d_out, int out_size) {
    const float* x  = (const float*)d_in[0];
    const void*  ei = d_in[1];
    const float* ew = (const float*)d_in[2];
    const float* W1 = (const float*)d_in[3];
    const float* b1 = (const float*)d_in[4];
    const float* W2 = (const float*)d_in[5];
    const float* b2 = (const float*)d_in[6];
    const float* W3 = (const float*)d_in[7];
    const float* b3 = (const float*)d_in[8];
    float* out = (float*)d_out;

    float *t, *h1, *c, *d1, *d2;
    int2 *pk1, *pk2;
    cudaGetSymbolAddress((void**)&t,   g_t);
    cudaGetSymbolAddress((void**)&h1,  g_h1);
    cudaGetSymbolAddress((void**)&c,   g_c);
    cudaGetSymbolAddress((void**)&d1,  g_d1);
    cudaGetSymbolAddress((void**)&d2,  g_d2);
    cudaGetSymbolAddress((void**)&pk1, g_pk1);
    cudaGetSymbolAddress((void**)&pk2, g_pk2);

    const int TB = 256;
    const int NB_N = (NN + TB - 1) / TB;
    const int NB_E = (EE + TB - 1) / TB;
    const int NB_W = (NN * 32 + TB - 1) / TB;   // one warp per node
    dim3 gg128((NN + 63) / 64, 2);
    dim3 gg40((NN + 63) / 64, 1);

    // graph prep (CSR by dst + both normalizations, pre-multiplied slot weights)
    detect_kernel<<<1, TB>>>((const int*)ei);
    zero_kernel<<<NB_N, TB>>>();
    count_kernel<<<NB_E, TB>>>(ei, ew);
    dinv_kernel<<<NB_N, TB>>>();
    scan_kernel<<<1, 1024>>>();
    fill_kernel<<<NB_E, TB>>>(ei, ew);

    // conv1: h1 = relu(agg_1(x@W1) + b1)
    gemm_kernel<<<gg128, TB>>>(x, W1, t, 128);
    agg128_kernel<<<NB_W, TB>>>(t, h1, pk1, d1, b1, nullptr, 0);

    // conv2 (crf): c = 0.1*h1 + agg_w(h1@W2) + b2
    gemm_kernel<<<gg128, TB>>>(h1, W2, t, 128);
    agg128_kernel<<<NB_W, TB>>>(t, c, pk2, d2, b2, h1, 1);

    // conv3: out = log_softmax(agg_1(c@W3) + b3)
    gemm_kernel<<<gg40, TB>>>(c, W3, t, 40);
    agg40_lsm_kernel<<<NB_W, TB>>>(t, out, pk1, d1, b3);
}